// round 6
// baseline (speedup 1.0000x reference)
#include <cuda_runtime.h>
#include <math.h>

#define N_IN   512
#define N_OUT  10
#define D_OUT  16
#define D_IN   8
#define NJD    (N_OUT * D_OUT)    // 160 output elements -> 160 blocks
#define NWARP  16
#define NTHR   (NWARP * 32)       // 512 threads
#define N_PER_WARP (N_IN / NWARP) // 32 n-rows per warp
#define EPS    1e-7f

// One block per (j,d), 16 warps. Lane mapping within a warp:
//   pair = lane>>1 (0..15) selects n-row offset, half = lane&1 selects k-half.
// Warp w covers n in [w*32, (w+1)*32): 2 iterations * (1 W float4 + 1 x float4)
// = 4 independent LDG.128 per lane -> ~16-cycle issue, single latency exposure,
// 16 eligible warps per SM to hide it.
__global__ __launch_bounds__(NTHR) void digitcaps_per_jd(
    const float* __restrict__ x,   // (512, 8)
    const float* __restrict__ W,   // (512, 160, 8) contiguous
    float* __restrict__ out)       // 160 floats
{
    __shared__ float s_warp[NWARP];

    const int jd   = blockIdx.x;          // 0..159
    const int warp = threadIdx.x >> 5;    // 0..15
    const int lane = threadIdx.x & 31;
    const int pair = lane >> 1;           // 0..15
    const int half = lane & 1;            // 0..1

    const int n0 = warp * N_PER_WARP + pair;

    // Batch the 4 loads (independent addresses).
    float4 w4[2], x4[2];
#pragma unroll
    for (int i = 0; i < 2; ++i) {
        const int n = n0 + i * 16;
        w4[i] = *reinterpret_cast<const float4*>(
            W + ((size_t)n * NJD + jd) * D_IN + half * 4);
        x4[i] = *reinterpret_cast<const float4*>(
            x + (size_t)n * D_IN + half * 4);
    }

    // Two independent accumulator chains.
    float acc0 = 0.0f, acc1 = 0.0f;
    acc0 = fmaf(w4[0].x, x4[0].x, acc0);
    acc0 = fmaf(w4[0].y, x4[0].y, acc0);
    acc0 = fmaf(w4[0].z, x4[0].z, acc0);
    acc0 = fmaf(w4[0].w, x4[0].w, acc0);
    acc1 = fmaf(w4[1].x, x4[1].x, acc1);
    acc1 = fmaf(w4[1].y, x4[1].y, acc1);
    acc1 = fmaf(w4[1].z, x4[1].z, acc1);
    acc1 = fmaf(w4[1].w, x4[1].w, acc1);
    float acc = acc0 + acc1;

    // warp butterfly reduce (16 n-rows x 2 k-halves)
#pragma unroll
    for (int off = 16; off > 0; off >>= 1)
        acc += __shfl_xor_sync(0xFFFFFFFFu, acc, off);

    if (lane == 0) s_warp[warp] = acc;
    __syncthreads();

    // warp 0 finishes: lanes 0-15 hold the 16 warp partials, 4-level shfl,
    // lane 0 applies squash and stores.
    if (warp == 0) {
        float s = (lane < NWARP) ? s_warp[lane] : 0.0f;
#pragma unroll
        for (int off = 8; off > 0; off >>= 1)
            s += __shfl_xor_sync(0xFFFFFFFFu, s, off);

        if (lane == 0) {
            s *= (1.0f / (float)N_IN);
            const float sq   = s * s;
            const float norm = s / (sqrtf(sq + EPS) + EPS);
            out[jd] = (sq / (1.0f + sq)) * norm;
        }
    }
}

extern "C" void kernel_launch(void* const* d_in, const int* in_sizes, int n_in,
                              void* d_out, int out_size)
{
    const float* x;
    const float* W;
    if (in_sizes[0] == N_IN * D_IN) {
        x = (const float*)d_in[0];
        W = (const float*)d_in[1];
    } else {
        x = (const float*)d_in[1];
        W = (const float*)d_in[0];
    }
    float* out = (float*)d_out;

    digitcaps_per_jd<<<NJD, NTHR>>>(x, W, out);
}